// round 8
// baseline (speedup 1.0000x reference)
#include <cuda_runtime.h>
#include <math.h>

#define N_WL 262144

// ---------------- compile-time line constants (from reference LINES/MASS) -------------
__constant__ float c_nu0[10]  = {254.0f, 280.0f, 310.0f, 940.0f, 1130.0f,
                                 1380.0f, 1400.0f, 1600.0f, 2000.0f, 2700.0f};
__constant__ float c_str[10]  = {1.15e-17f, 5e-18f, 1.9e-19f, 2.5e-23f, 8.2e-24f,
                                 1.8e-22f, 3.5e-25f, 7.8e-26f, 4.2e-24f, 1.2e-24f};
__constant__ float c_wid[10]  = {2.0f, 3.0f, 2.5f, 3.0f, 2.5f, 4.0f, 3.0f, 2.5f, 4.0f, 3.5f};
__constant__ float c_tex[10]  = {0.05f, 0.04f, 0.03f, 0.4f, 0.35f, 0.45f, 0.5f, 0.48f, 0.52f, 0.49f};
__constant__ float c_mass[10] = {48.f, 48.f, 48.f, 18.f, 18.f, 18.f, 44.f, 44.f, 44.f, 44.f};

// ---------------- math helpers --------------------------------------------------------
__device__ __forceinline__ float voigt_core(float x, float y) {
    // Humlicek-style piecewise rational approximation, matching reference exactly.
    float ax = fabsf(x);
    float s  = ax + y;
    float x2 = x * x;
    float y2 = y * y;
    if (s >= 15.0f) {
        float dr = 0.5f + y2 - x2;
        float di = -2.0f * x * y;
        float num = y * dr + 2.0f * x2 * y;
        return 0.5641896f * num / (dr * dr + di * di);
    } else if (ax >= 5.5f) {
        float ur = y2 - x2;
        float ui = -2.0f * x * y;
        float Ar = 1.410474f + 0.5641896f * ur;
        float Ai = 0.5641896f * ui;
        float nr = y * Ar + x * Ai;
        float ni = y * Ai - x * Ar;
        float dr = 0.75f + 3.0f * ur + (ur * ur - ui * ui);
        float di = 3.0f * ui + 2.0f * ur * ui;
        return (nr * dr + ni * di) / (dr * dr + di * di);
    } else {
        return expf(-x2) * cosf(2.0f * x * y) * 0.5641895835f
             + 0.6366197723f * y * sinf(x2) / (x2 + y2 + 1e-10f);
    }
}

__device__ __forceinline__ float softplus_f(float z) {
    return fmaxf(z, 0.0f) + log1pf(expf(-fabsf(z)));
}
__device__ __forceinline__ float sigmoid_f(float z) {
    return 1.0f / (1.0f + expf(-z));
}
__device__ __forceinline__ float silu_f(float z) {
    return z * sigmoid_f(z);
}

// ---------------- fused kernel: per-block prep + streaming pass -----------------------
// Each block redundantly computes the tiny sequential prologue (line params, h[32],
// cross[:8] -> mixing MLP -> m2[64]) in shared memory, then streams its 256
// wavelengths. Eliminates the separate prep kernel + serialization gap, and the
// scalar (1 wl/thread) layout gives ~4x the resident warps of the float4 version.
__global__ __launch_bounds__(256) void fused_kernel(
    const float* __restrict__ wl,
    const float* __restrict__ Tp,  const float* __restrict__ Pp,
    const float* __restrict__ o3p, const float* __restrict__ h2op, const float* __restrict__ co2p,
    const float* __restrict__ mw1, const float* __restrict__ mb1,
    const float* __restrict__ mw2, const float* __restrict__ mb2,
    const float* __restrict__ mw3, const float* __restrict__ mb3,
    const float* __restrict__ cw1, const float* __restrict__ cb1,
    const float* __restrict__ cw2, const float* __restrict__ cb2,
    float* __restrict__ out)
{
    __shared__ float s_nu0[10], s_is[10], s_y[10], s_amp[10];
    __shared__ float s_h[32], s_mf[10], s_m1[64], s_m[64];

    const int t = threadIdx.x;

    // ---- Phase A: prologue (redundant per block; tiny) ----
    const float T = Tp[0];
    const float P = Pp[0];
    const float invT = 273.15f / (T + 1e-12f);

    if (t < 10) {
        float sT    = c_str[t] * powf(invT, c_tex[t]);
        float gL    = c_wid[t] * (P / (101325.0f + 1e-12f)) * sqrtf(invT);
        float gD    = c_nu0[t] / 299792458.0f *
                      sqrtf(2.0f * 1.380649e-23f * T * 6.02214076e23f / (c_mass[t] + 1e-12f));
        float sigma = gD / (1.1774100f + 1e-12f);       // sqrt(2 ln 2)
        float conc  = (t < 3) ? o3p[0] : ((t < 6) ? h2op[0] : co2p[0]);
        float is    = 1.0f / (sigma + 1e-12f);
        s_nu0[t] = c_nu0[t];
        s_is[t]  = is;
        s_y[t]   = gL * is;
        s_amp[t] = conc * sT / (sigma * 1.7724539f + 1e-12f);
    }
    if (t >= 32 && t < 64) {
        int j = t - 32;
        float z = cb1[j];
        z = fmaf(T / (273.15f + 1e-12f),   cw1[0 * 32 + j], z);
        z = fmaf(P / (101325.0f + 1e-12f), cw1[1 * 32 + j], z);
        z = fmaf(h2op[0],                  cw1[2 * 32 + j], z);
        z = fmaf(1.0f,                     cw1[3 * 32 + j], z);
        s_h[j] = silu_f(z);
    }
    __syncthreads();

    if (t < 8) {
        float w = wl[t];
        float c = 0.0f;
        #pragma unroll
        for (int l = 0; l < 10; l++) {
            float x = (w - s_nu0[l]) * s_is[l];
            c = fmaf(s_amp[l], voigt_core(x, s_y[l]), c);
        }
        float z = cb2[t];
        #pragma unroll
        for (int k = 0; k < 32; k++)
            z = fmaf(s_h[k], cw2[k * N_WL + t], z);
        s_mf[2 + t] = c + softplus_f(z);
    }
    if (t == 8) s_mf[0] = T / (273.15f + 1e-12f);
    if (t == 9) s_mf[1] = P / (101325.0f + 1e-12f);
    __syncthreads();

    if (t < 64) {
        float z = mb1[t];
        #pragma unroll
        for (int j = 0; j < 10; j++)
            z = fmaf(s_mf[j], mw1[j * 64 + t], z);
        s_m1[t] = silu_f(z);
    }
    __syncthreads();

    if (t < 64) {
        float z = mb2[t];
        #pragma unroll
        for (int j = 0; j < 64; j++)
            z = fmaf(s_m1[j], mw2[j * 64 + t], z);
        s_m[t] = silu_f(z);
    }
    __syncthreads();

    // ---- Phase B: streaming per-wavelength pass ----
    const int i = blockIdx.x * 256 + t;

    float w = wl[i];
    float cross = 0.0f;

    #pragma unroll 1
    for (int l = 0; l < 10; l++) {
        float x = (w - s_nu0[l]) * s_is[l];
        cross = fmaf(s_amp[l], voigt_core(x, s_y[l]), cross);
    }

    // continuum = softplus(h @ cont_w2 + cont_b2)
    float a0 = cb2[i];
    float a1 = 0.0f;
    #pragma unroll
    for (int k = 0; k < 32; k += 2) {
        a0 = fmaf(s_h[k],     cw2[k * N_WL + i],       a0);
        a1 = fmaf(s_h[k + 1], cw2[(k + 1) * N_WL + i], a1);
    }
    cross += softplus_f(a0 + a1);

    // mixing = sigmoid(m2 @ mix_w3 + mix_b3)
    float z0 = mb3[i];
    float z1 = 0.0f;
    float z2 = 0.0f;
    float z3 = 0.0f;
    #pragma unroll
    for (int k = 0; k < 64; k += 4) {
        z0 = fmaf(s_m[k],     mw3[k * N_WL + i],       z0);
        z1 = fmaf(s_m[k + 1], mw3[(k + 1) * N_WL + i], z1);
        z2 = fmaf(s_m[k + 2], mw3[(k + 2) * N_WL + i], z2);
        z3 = fmaf(s_m[k + 3], mw3[(k + 3) * N_WL + i], z3);
    }
    float mz = (z0 + z1) + (z2 + z3);

    out[i] = cross * (1.0f + 0.1f * (sigmoid_f(mz) - 0.5f));
}

// ---------------- launch --------------------------------------------------------------
extern "C" void kernel_launch(void* const* d_in, const int* in_sizes, int n_in,
                              void* d_out, int out_size)
{
    const float* wl   = (const float*)d_in[0];
    const float* Tp   = (const float*)d_in[1];
    const float* Pp   = (const float*)d_in[2];
    const float* o3   = (const float*)d_in[3];
    const float* h2o  = (const float*)d_in[4];
    const float* co2  = (const float*)d_in[5];
    const float* mw1  = (const float*)d_in[6];
    const float* mb1  = (const float*)d_in[7];
    const float* mw2  = (const float*)d_in[8];
    const float* mb2  = (const float*)d_in[9];
    const float* mw3  = (const float*)d_in[10];
    const float* mb3  = (const float*)d_in[11];
    const float* cw1  = (const float*)d_in[12];
    const float* cb1  = (const float*)d_in[13];
    const float* cw2  = (const float*)d_in[14];
    const float* cb2  = (const float*)d_in[15];

    fused_kernel<<<N_WL / 256, 256>>>(
        wl, Tp, Pp, o3, h2o, co2,
        mw1, mb1, mw2, mb2, mw3, mb3,
        cw1, cb1, cw2, cb2,
        (float*)d_out);
}

// round 9
// speedup vs baseline: 1.3785x; 1.3785x over previous
#include <cuda_runtime.h>
#include <math.h>

#define N_WL 262144
#define NV4  (N_WL / 4)

// ---------------- compile-time line constants (from reference LINES/MASS) -------------
__constant__ float c_nu0[10]  = {254.0f, 280.0f, 310.0f, 940.0f, 1130.0f,
                                 1380.0f, 1400.0f, 1600.0f, 2000.0f, 2700.0f};
__constant__ float c_str[10]  = {1.15e-17f, 5e-18f, 1.9e-19f, 2.5e-23f, 8.2e-24f,
                                 1.8e-22f, 3.5e-25f, 7.8e-26f, 4.2e-24f, 1.2e-24f};
__constant__ float c_wid[10]  = {2.0f, 3.0f, 2.5f, 3.0f, 2.5f, 4.0f, 3.0f, 2.5f, 4.0f, 3.5f};
__constant__ float c_tex[10]  = {0.05f, 0.04f, 0.03f, 0.4f, 0.35f, 0.45f, 0.5f, 0.48f, 0.52f, 0.49f};
__constant__ float c_mass[10] = {48.f, 48.f, 48.f, 18.f, 18.f, 18.f, 44.f, 44.f, 44.f, 44.f};

// ---------------- device-global scratch ----------------------------------------------
__device__ float g_nu0[10], g_is[10], g_y[10], g_amp[10];
__device__ float g_h[32];
__device__ float g_m2[64];

// ---------------- math helpers --------------------------------------------------------
__device__ __forceinline__ float voigt_core(float x, float y) {
    float ax = fabsf(x);
    float s  = ax + y;
    float x2 = x * x;
    float y2 = y * y;
    if (s >= 15.0f) {
        float dr = 0.5f + y2 - x2;
        float di = -2.0f * x * y;
        float num = y * dr + 2.0f * x2 * y;
        return 0.5641896f * num / (dr * dr + di * di);
    } else if (ax >= 5.5f) {
        float ur = y2 - x2;
        float ui = -2.0f * x * y;
        float Ar = 1.410474f + 0.5641896f * ur;
        float Ai = 0.5641896f * ui;
        float nr = y * Ar + x * Ai;
        float ni = y * Ai - x * Ar;
        float dr = 0.75f + 3.0f * ur + (ur * ur - ui * ui);
        float di = 3.0f * ui + 2.0f * ur * ui;
        return (nr * dr + ni * di) / (dr * dr + di * di);
    } else {
        return expf(-x2) * cosf(2.0f * x * y) * 0.5641895835f
             + 0.6366197723f * y * sinf(x2) / (x2 + y2 + 1e-10f);
    }
}

__device__ __forceinline__ float softplus_f(float z) {
    return fmaxf(z, 0.0f) + log1pf(expf(-fabsf(z)));
}
__device__ __forceinline__ float sigmoid_f(float z) {
    return 1.0f / (1.0f + expf(-z));
}
__device__ __forceinline__ float silu_f(float z) {
    return z * sigmoid_f(z);
}

// ---------------- kernel 1: sequential prep (1 block, 64 threads) ---------------------
__global__ void prep_kernel(
    const float* __restrict__ wl,
    const float* __restrict__ Tp,  const float* __restrict__ Pp,
    const float* __restrict__ o3p, const float* __restrict__ h2op, const float* __restrict__ co2p,
    const float* __restrict__ mw1, const float* __restrict__ mb1,
    const float* __restrict__ mw2, const float* __restrict__ mb2,
    const float* __restrict__ cw1, const float* __restrict__ cb1,
    const float* __restrict__ cw2, const float* __restrict__ cb2)
{
    __shared__ float s_nu0[10], s_is[10], s_y[10], s_amp[10];
    __shared__ float s_h[32], s_mf[10], s_m1[64];

    const int t = threadIdx.x;
    const float T = Tp[0];
    const float P = Pp[0];
    const float invT = 273.15f / (T + 1e-12f);

    if (t < 10) {
        float sT    = c_str[t] * powf(invT, c_tex[t]);
        float gL    = c_wid[t] * (P / (101325.0f + 1e-12f)) * sqrtf(invT);
        float gD    = c_nu0[t] / 299792458.0f *
                      sqrtf(2.0f * 1.380649e-23f * T * 6.02214076e23f / (c_mass[t] + 1e-12f));
        float sigma = gD / (1.1774100f + 1e-12f);
        float conc  = (t < 3) ? o3p[0] : ((t < 6) ? h2op[0] : co2p[0]);
        float is    = 1.0f / (sigma + 1e-12f);
        float yv    = gL * is;
        float amp   = conc * sT / (sigma * 1.7724539f + 1e-12f);
        s_nu0[t] = c_nu0[t];  s_is[t] = is;  s_y[t] = yv;  s_amp[t] = amp;
        g_nu0[t] = c_nu0[t];  g_is[t] = is;  g_y[t] = yv;  g_amp[t] = amp;
    }

    if (t < 32) {
        float z = cb1[t];
        z = fmaf(T / (273.15f + 1e-12f),   cw1[0 * 32 + t], z);
        z = fmaf(P / (101325.0f + 1e-12f), cw1[1 * 32 + t], z);
        z = fmaf(h2op[0],                  cw1[2 * 32 + t], z);
        z = fmaf(1.0f,                     cw1[3 * 32 + t], z);
        float h = silu_f(z);
        s_h[t] = h;
        g_h[t] = h;
    }
    __syncthreads();

    if (t < 8) {
        float w = wl[t];
        float c = 0.0f;
        #pragma unroll
        for (int l = 0; l < 10; l++) {
            float x = (w - s_nu0[l]) * s_is[l];
            c = fmaf(s_amp[l], voigt_core(x, s_y[l]), c);
        }
        float z = cb2[t];
        #pragma unroll
        for (int k = 0; k < 32; k++)
            z = fmaf(s_h[k], cw2[k * N_WL + t], z);
        s_mf[2 + t] = c + softplus_f(z);
    }
    if (t == 0) {
        s_mf[0] = T / (273.15f + 1e-12f);
        s_mf[1] = P / (101325.0f + 1e-12f);
    }
    __syncthreads();

    if (t < 64) {
        float z = mb1[t];
        #pragma unroll
        for (int j = 0; j < 10; j++)
            z = fmaf(s_mf[j], mw1[j * 64 + t], z);
        s_m1[t] = silu_f(z);
    }
    __syncthreads();

    if (t < 64) {
        float z = mb2[t];
        #pragma unroll
        for (int j = 0; j < 64; j++)
            z = fmaf(s_m1[j], mw2[j * 64 + t], z);
        g_m2[t] = silu_f(z);
    }
}

// ---------------- kernel 2: streaming pass with explicit load batching ----------------
// float4 per thread (65536 threads). Chunks of 16 independent float4 loads are
// issued before their FMAs so each warp keeps ~8KB in flight — enough to cover
// DRAM latency at the LTS throughput cap despite only ~14 warps/SM residency.
__global__ __launch_bounds__(128) void spec_kernel(
    const float4* __restrict__ wl,
    const float4* __restrict__ cont_w2, const float4* __restrict__ cont_b2,
    const float4* __restrict__ mix_w3,  const float4* __restrict__ mix_b3,
    float4* __restrict__ out)
{
    __shared__ float s_nu0[10], s_is[10], s_y[10], s_amp[10];
    __shared__ float s_h[32], s_m[64];

    const int t = threadIdx.x;
    if (t < 10) { s_nu0[t] = g_nu0[t]; s_is[t] = g_is[t]; s_y[t] = g_y[t]; s_amp[t] = g_amp[t]; }
    if (t < 32) s_h[t] = g_h[t];
    if (t < 64) s_m[t] = g_m2[t];
    __syncthreads();

    const int i = blockIdx.x * 128 + t;   // 0 .. NV4-1

    // ---- continuum: softplus(h @ cont_w2 + cont_b2), chunks of 16 batched loads ----
    float4 a = cont_b2[i];
    float4 a1 = make_float4(0.f, 0.f, 0.f, 0.f);
    #pragma unroll
    for (int kk = 0; kk < 32; kk += 16) {
        float4 v[16];
        #pragma unroll
        for (int j = 0; j < 16; j++)
            v[j] = cont_w2[(kk + j) * NV4 + i];
        #pragma unroll
        for (int j = 0; j < 16; j += 2) {
            float h0 = s_h[kk + j], h1 = s_h[kk + j + 1];
            a.x  = fmaf(h0, v[j].x,     a.x);
            a.y  = fmaf(h0, v[j].y,     a.y);
            a.z  = fmaf(h0, v[j].z,     a.z);
            a.w  = fmaf(h0, v[j].w,     a.w);
            a1.x = fmaf(h1, v[j + 1].x, a1.x);
            a1.y = fmaf(h1, v[j + 1].y, a1.y);
            a1.z = fmaf(h1, v[j + 1].z, a1.z);
            a1.w = fmaf(h1, v[j + 1].w, a1.w);
        }
    }

    // ---- mixing: sigmoid(m2 @ mix_w3 + mix_b3), chunks of 16 batched loads ----
    float4 z = mix_b3[i];
    float4 z1 = make_float4(0.f, 0.f, 0.f, 0.f);
    #pragma unroll
    for (int kk = 0; kk < 64; kk += 16) {
        float4 v[16];
        #pragma unroll
        for (int j = 0; j < 16; j++)
            v[j] = mix_w3[(kk + j) * NV4 + i];
        #pragma unroll
        for (int j = 0; j < 16; j += 2) {
            float m0 = s_m[kk + j], m1 = s_m[kk + j + 1];
            z.x  = fmaf(m0, v[j].x,     z.x);
            z.y  = fmaf(m0, v[j].y,     z.y);
            z.z  = fmaf(m0, v[j].z,     z.z);
            z.w  = fmaf(m0, v[j].w,     z.w);
            z1.x = fmaf(m1, v[j + 1].x, z1.x);
            z1.y = fmaf(m1, v[j + 1].y, z1.y);
            z1.z = fmaf(m1, v[j + 1].z, z1.z);
            z1.w = fmaf(m1, v[j + 1].w, z1.w);
        }
    }

    // ---- Voigt line sum (compute-only; after loads so LDGs issue first) ----
    float4 w4 = wl[i];
    float wv[4] = {w4.x, w4.y, w4.z, w4.w};
    float cr[4] = {0.f, 0.f, 0.f, 0.f};
    #pragma unroll 1
    for (int l = 0; l < 10; l++) {
        float nu0 = s_nu0[l], is = s_is[l], y = s_y[l], amp = s_amp[l];
        #pragma unroll
        for (int j = 0; j < 4; j++) {
            float x = (wv[j] - nu0) * is;
            cr[j] = fmaf(amp, voigt_core(x, y), cr[j]);
        }
    }

    float c0 = cr[0] + softplus_f(a.x + a1.x);
    float c1 = cr[1] + softplus_f(a.y + a1.y);
    float c2 = cr[2] + softplus_f(a.z + a1.z);
    float c3 = cr[3] + softplus_f(a.w + a1.w);

    float4 o;
    o.x = c0 * (1.0f + 0.1f * (sigmoid_f(z.x + z1.x) - 0.5f));
    o.y = c1 * (1.0f + 0.1f * (sigmoid_f(z.y + z1.y) - 0.5f));
    o.z = c2 * (1.0f + 0.1f * (sigmoid_f(z.z + z1.z) - 0.5f));
    o.w = c3 * (1.0f + 0.1f * (sigmoid_f(z.w + z1.w) - 0.5f));
    out[i] = o;
}

// ---------------- launch --------------------------------------------------------------
extern "C" void kernel_launch(void* const* d_in, const int* in_sizes, int n_in,
                              void* d_out, int out_size)
{
    const float* wl   = (const float*)d_in[0];
    const float* Tp   = (const float*)d_in[1];
    const float* Pp   = (const float*)d_in[2];
    const float* o3   = (const float*)d_in[3];
    const float* h2o  = (const float*)d_in[4];
    const float* co2  = (const float*)d_in[5];
    const float* mw1  = (const float*)d_in[6];
    const float* mb1  = (const float*)d_in[7];
    const float* mw2  = (const float*)d_in[8];
    const float* mb2  = (const float*)d_in[9];
    const float* mw3  = (const float*)d_in[10];
    const float* mb3  = (const float*)d_in[11];
    const float* cw1  = (const float*)d_in[12];
    const float* cb1  = (const float*)d_in[13];
    const float* cw2  = (const float*)d_in[14];
    const float* cb2  = (const float*)d_in[15];

    prep_kernel<<<1, 64>>>(wl, Tp, Pp, o3, h2o, co2,
                           mw1, mb1, mw2, mb2, cw1, cb1, cw2, cb2);

    spec_kernel<<<NV4 / 128, 128>>>(
        (const float4*)wl,
        (const float4*)cw2, (const float4*)cb2,
        (const float4*)mw3, (const float4*)mb3,
        (float4*)d_out);
}